// round 11
// baseline (speedup 1.0000x reference)
#include <cuda_runtime.h>

#define CROP 14
#define B_ 4
#define N_ 256
#define H_ 256
#define W_ 256
#define C_ 256
#define CQ (C_ / 4)          // float4 quads per pixel = 64

// 196 positions per box, split across 7 CTAs of 28 positions each.
#define PARTS 7
#define POS_PER_PART 28

__device__ __forceinline__ void axis_sample(float lo, float hi, int i,
                                            int& i0, int& i1, float& w, float& v)
{
    // Replicate reference math in float32:
    //   n1 = lo/255 ; n2 = (hi-1)/255 ; t = i/13 ; s = (n1 + (n2-n1)*t) * 255
    const float t  = (float)i / 13.0f;
    const float n1 = lo / 255.0f;
    const float n2 = (hi - 1.0f) / 255.0f;
    const float s  = (n1 + (n2 - n1) * t) * 255.0f;
    v = (s >= 0.0f && s <= 255.0f) ? 1.0f : 0.0f;
    const float f0 = floorf(s);
    w = s - f0;
    i0 = (int)f0;
    i1 = i0 + 1;
    i0 = min(max(i0, 0), H_ - 1);
    i1 = min(max(i1, 0), H_ - 1);
}

__global__ __launch_bounds__(256) void roi_align_kernel(
    const float* __restrict__ boxes,
    const float* __restrict__ fpn,
    float* __restrict__ out)
{
    const int blk  = blockIdx.y;       // box index: b * N_ + n (box-major)
    const int part = blockIdx.x;       // 0..6
    const int b    = blk >> 8;         // N_ = 256
    const int base = part * POS_PER_PART;

    const int tid = threadIdx.x;
    const int sub = tid >> 6;   // position within each group of 4
    const int q   = tid & 63;   // float4 index within C

    // Every thread computes its own positions' sampling data inline in
    // registers: no shared memory, no barrier, warps fully independent.
    // The redundant ALU (64 threads repeat the same axis math) is free —
    // ALU pipe is at 10% — and the first image load issues ~30 instrs
    // after the boxes load instead of after an all-warp barrier chain.
    const float4 bx = __ldg(&((const float4*)boxes)[blk]);   // (x1, y1, x2, y2)

    const float4* img  = (const float4*)(fpn) + (size_t)b * (H_ * W_ * CQ);
    float4*       outp = (float4*)(out) + ((size_t)blk * (CROP * CROP) + base) * CQ;

    #pragma unroll
    for (int pb = 0; pb < POS_PER_PART; pb += 4) {
        const int pos = base + pb + sub;
        const int py  = pos / CROP;
        const int px  = pos - py * CROP;

        int y0, y1; float wy, vy;
        int x0, x1; float wx, vx;
        axis_sample(bx.y, bx.w, py, y0, y1, wy, vy);
        axis_sample(bx.x, bx.z, px, x0, x1, wx, vx);

        const float4 tl = img[(y0 * W_ + x0) * CQ + q];
        const float4 tr = img[(y0 * W_ + x1) * CQ + q];
        const float4 bl = img[(y1 * W_ + x0) * CQ + q];
        const float4 br = img[(y1 * W_ + x1) * CQ + q];

        const float v   = vy * vx;
        const float w00 = (1.0f - wy) * (1.0f - wx) * v;
        const float w01 = (1.0f - wy) * wx * v;
        const float w10 = wy * (1.0f - wx) * v;
        const float w11 = wy * wx * v;

        float4 r;
        r.x = tl.x * w00 + tr.x * w01 + bl.x * w10 + br.x * w11;
        r.y = tl.y * w00 + tr.y * w01 + bl.y * w10 + br.y * w11;
        r.z = tl.z * w00 + tr.z * w01 + bl.z * w10 + br.z * w11;
        r.w = tl.w * w00 + tr.w * w01 + bl.w * w10 + br.w * w11;

        // Streaming store: output is never re-read; keep the image L2-resident.
        __stcs(&outp[(pb + sub) * CQ + q], r);
    }
}

extern "C" void kernel_launch(void* const* d_in, const int* in_sizes, int n_in,
                              void* d_out, int out_size) {
    const float* boxes = (const float*)d_in[0];
    const float* fpn   = (const float*)d_in[1];
    if (n_in >= 2 && in_sizes[0] > in_sizes[1]) {
        boxes = (const float*)d_in[1];
        fpn   = (const float*)d_in[0];
    }
    dim3 grid(PARTS, B_ * N_);
    roi_align_kernel<<<grid, 256>>>(boxes, fpn, (float*)d_out);
}